// round 8
// baseline (speedup 1.0000x reference)
#include <cuda_runtime.h>
#include <cuda_bf16.h>
#include <math.h>

// ---------------------------------------------------------------------------
// ClusterAttn: b=1, D=32, H=128, W=128, C=96, P=4, FEAD=64, K=64
// Launches: init0,init1,init2 (tiny; also makes k1 the ncu-profiled 4th launch)
//  k1   : dwc stage1  y_t[p] = dot_c(x[p,:], w[:,t]) -> bf16 maps
//  k2   : 27-tap gather -> fea (raw) + column sum-of-squares
//  k4b  : soft-assign logits (inv folded into centroids), exp -> expl + colsum
//  k5a  : newcacc = E^T @ fea  (32-token tiles, 256 blocks, atomics)
//  k5b  : normalize -> kv -> fold M/d
//  kAttn: logits -> softmax -> attn@v -> scatter to o1
//  k9   : upc conv (1->96) + bias + residual x
// ---------------------------------------------------------------------------

#define DD 32
#define HH 128
#define WW 128
#define NP (DD*HH*WW)      // 524288 voxels
#define CC 96
#define NT 8192            // tokens
#define FE 64              // FEAD
#define KK 64              // clusters

// ------------------------- scratch (device globals) -------------------------
__device__ __align__(256) __nv_bfloat16 g_yb[27*NP];   // 28.3 MB
__device__ __align__(256) float g_fea[NT*FE];          // raw (un-normalized)
__device__ __align__(256) float g_expl[NT*KK];
__device__ __align__(256) float g_o1[NP];
__device__ __align__(256) float g_ssq[FE];
__device__ __align__(256) float g_colsum[KK];
__device__ __align__(256) float g_newcacc[KK*FE];
__device__ __align__(256) float g_v[KK*FE];
__device__ __align__(256) float g_M[KK*FE];
__device__ __align__(256) float g_d[KK];

// ------------------------- f32x2 packed helpers -----------------------------
using u64 = unsigned long long;
__device__ __forceinline__ u64 pk2(float a, float b) {
    u64 r; asm("mov.b64 %0,{%1,%2};" : "=l"(r) : "f"(a), "f"(b)); return r;
}
__device__ __forceinline__ float2 upk2(u64 v) {
    float2 r; asm("mov.b64 {%0,%1},%2;" : "=f"(r.x), "=f"(r.y) : "l"(v)); return r;
}
__device__ __forceinline__ u64 ffma2(u64 a, u64 b, u64 c) {
    u64 d; asm("fma.rn.f32x2 %0,%1,%2,%3;" : "=l"(d) : "l"(a), "l"(b), "l"(c)); return d;
}

// ------------------------- init kernels (also launch-order shims) -----------
__global__ void init0() {
    int t = threadIdx.x;
    if (t < FE) g_ssq[t] = 0.f;
    if (t < KK) g_colsum[t] = 0.f;
}
__global__ void init1() {
    int t = threadIdx.x;
    for (int i = t; i < KK*FE/2; i += 256) g_newcacc[i] = 0.f;
}
__global__ void init2() {
    int t = threadIdx.x;
    for (int i = t; i < KK*FE/2; i += 256) g_newcacc[KK*FE/2 + i] = 0.f;
}

// ------------------------- k1: dwc stage1  Y[NP,27] = X[NP,96] @ W[96,27] ----
// Block 128 threads / 768 voxels; thread owns 3 voxel-pairs at interleaved
// columns (2*lane + 64*s within its warp's 192-voxel region), so each weight
// broadcast LDS.64 feeds 3 FFMA2. x staged via shared in 8-channel slabs.
#define K1_NV 768
#define K1_GRID ((NP + K1_NV - 1) / K1_NV)   // 683 (last block partial)
__global__ __launch_bounds__(128) void k1_dwc1(const float* __restrict__ x,
                                               const float* __restrict__ dwc_w) {
    __shared__ u64   w2[CC*27];          // (w,w) pairs, 20.25 KB
    __shared__ float xs[8][K1_NV + 4];   // pitch 772 = 4 (mod 32): conflict-free
    int tid  = threadIdx.x;
    int lane = tid & 31, wrp = tid >> 5;
    for (int i = tid; i < CC*27; i += 128) { float v = dwc_w[i]; w2[i] = pk2(v, v); }

    int vbase = blockIdx.x * K1_NV;
    int colbase = wrp * 192 + 2 * lane;  // within-block column of pair s: +64*s

    u64 acc[27][3];
#pragma unroll
    for (int t = 0; t < 27; t++) { acc[t][0] = 0ull; acc[t][1] = 0ull; acc[t][2] = 0ull; }

#pragma unroll 1
    for (int cb = 0; cb < CC; cb += 8) {
        __syncthreads();
#pragma unroll
        for (int it = 0; it < 12; it++) {      // stage 768 vox x 8 ch, coalesced
            int e = it*128 + tid;
            int v = e >> 1, slot = e & 1;
            int vg = vbase + v;
            float4 val = make_float4(0.f, 0.f, 0.f, 0.f);
            if (vg < NP)
                val = *reinterpret_cast<const float4*>(
                    x + (size_t)vg*CC + cb + slot*4);
            xs[slot*4+0][v] = val.x;
            xs[slot*4+1][v] = val.y;
            xs[slot*4+2][v] = val.z;
            xs[slot*4+3][v] = val.w;
        }
        __syncthreads();
#pragma unroll
        for (int c = 0; c < 8; c++) {
            u64 xp0 = *reinterpret_cast<const u64*>(&xs[c][colbase]);
            u64 xp1 = *reinterpret_cast<const u64*>(&xs[c][colbase + 64]);
            u64 xp2 = *reinterpret_cast<const u64*>(&xs[c][colbase + 128]);
            const u64* wc = w2 + (cb + c)*27;
#pragma unroll
            for (int t = 0; t < 27; t++) {
                u64 w = wc[t];
                acc[t][0] = ffma2(xp0, w, acc[t][0]);
                acc[t][1] = ffma2(xp1, w, acc[t][1]);
                acc[t][2] = ffma2(xp2, w, acc[t][2]);
            }
        }
    }
    // stores: bf16x2 per pair, lanes consecutive -> fully coalesced
#pragma unroll
    for (int s = 0; s < 3; s++) {
        int cb0 = vbase + wrp*192 + s*64;     // 64-aligned region base
        if (cb0 < NP) {
#pragma unroll
            for (int t = 0; t < 27; t++) {
                float2 a = upk2(acc[t][s]);
                __nv_bfloat162 h = __floats2bfloat162_rn(a.x, a.y);
                *reinterpret_cast<__nv_bfloat162*>(
                    reinterpret_cast<char*>(g_yb) +
                    ((size_t)t*NP + cb0 + 2*lane)*2) = h;
            }
        }
    }
}

// ------------------------- k2: gather + fea (raw) + ssq ----------------------
__global__ __launch_bounds__(256) void k2_gather(const float* __restrict__ dwc_b) {
    __shared__ float ssq_s[FE];
    int tid = threadIdx.x;
    if (tid < FE) ssq_s[tid] = 0.f;
    __syncthreads();

    int p = blockIdx.x*256 + tid;
    int z = p >> 14, y = (p >> 7) & 127, xx = p & 127;

    float v = dwc_b[0];
#pragma unroll
    for (int kz = 0; kz < 3; kz++) {
        int zz = z + kz - 1; if ((unsigned)zz >= DD) continue;
#pragma unroll
        for (int ky = 0; ky < 3; ky++) {
            int yy = y + ky - 1; if ((unsigned)yy >= HH) continue;
#pragma unroll
            for (int kx = 0; kx < 3; kx++) {
                int xc = xx + kx - 1; if ((unsigned)xc >= WW) continue;
                int t = kz*9 + ky*3 + kx;
                v += __bfloat162float(g_yb[(size_t)t*NP + (zz*HH + yy)*WW + xc]);
            }
        }
    }
    int n = ((z >> 2) << 10) | ((y >> 2) << 5) | (xx >> 2);
    int f = ((z & 3) << 4) | ((y & 3) << 2) | (xx & 3);
    g_fea[n*FE + f] = v;
    atomicAdd(&ssq_s[f], v*v);
    __syncthreads();
    if (tid < FE) atomicAdd(&g_ssq[tid], ssq_s[tid]);
}

// ------------------------- k4b: soft-assign logits + exp + colsum -----------
__global__ __launch_bounds__(256) void k4b_logits(const float* __restrict__ cen) {
    __shared__ float4 cen_s[KK*16];
    __shared__ float inv_s[FE];
    __shared__ float cs_s[KK];
    int tid = threadIdx.x;
    if (tid < FE) inv_s[tid] = 1.f / fmaxf(sqrtf(g_ssq[tid]), 1e-12f);
    if (tid < KK) cs_s[tid] = 0.f;
    __syncthreads();
    for (int i = tid; i < KK*16; i += 256) {
        float4 w = reinterpret_cast<const float4*>(cen)[i];
        int f0 = (i*4) & 63;
        w.x *= inv_s[f0]; w.y *= inv_s[f0+1]; w.z *= inv_s[f0+2]; w.w *= inv_s[f0+3];
        cen_s[i] = w;
    }
    __syncthreads();

    int idx = blockIdx.x*256 + tid;              // (n, c-quarter)
    int n = idx >> 2, c0 = (idx & 3) * 16;
    float fr[FE];
    const float4* frp = reinterpret_cast<const float4*>(g_fea + n*FE);
#pragma unroll
    for (int f4 = 0; f4 < 16; f4++) {
        float4 v = frp[f4];
        fr[f4*4] = v.x; fr[f4*4+1] = v.y; fr[f4*4+2] = v.z; fr[f4*4+3] = v.w;
    }
#pragma unroll
    for (int cc = 0; cc < 16; cc++) {
        int c = c0 + cc;
        const float4* cr = cen_s + c*16;
        float l = 0.f;
#pragma unroll
        for (int f4 = 0; f4 < 16; f4++) {
            float4 w = cr[f4];
            l += fr[f4*4]*w.x + fr[f4*4+1]*w.y + fr[f4*4+2]*w.z + fr[f4*4+3]*w.w;
        }
        float e = __expf(l);
        g_expl[n*KK + c] = e;
        atomicAdd(&cs_s[c], e);
    }
    __syncthreads();
    if (tid < KK) atomicAdd(&g_colsum[tid], cs_s[tid]);
}

// ------------------------- k5a: newcacc = E^T @ fea (tiled GEMM) ------------
// Grid 256 blocks x 32 tokens. Register 4x4 outer-product tiles, atomics out.
__global__ __launch_bounds__(256) void k5a_gemm() {
    __shared__ float e_s[32][68];
    __shared__ float f_s[32][68];
    int tid = threadIdx.x;
    int n0 = blockIdx.x * 32;
#pragma unroll
    for (int k = 0; k < 8; k++) {                // coalesced tile loads
        int idx = k*256 + tid;
        int r = idx >> 6, c = idx & 63;
        e_s[r][c] = g_expl[(n0 + r)*KK + c];
        f_s[r][c] = g_fea [(n0 + r)*FE + c];
    }
    __syncthreads();

    int c0 = (tid >> 4) * 4;
    int f0 = (tid & 15) * 4;
    float a00=0,a01=0,a02=0,a03=0, a10=0,a11=0,a12=0,a13=0;
    float a20=0,a21=0,a22=0,a23=0, a30=0,a31=0,a32=0,a33=0;
#pragma unroll 8
    for (int n = 0; n < 32; n++) {
        float4 e4 = *reinterpret_cast<const float4*>(&e_s[n][c0]);
        float4 f4 = *reinterpret_cast<const float4*>(&f_s[n][f0]);
        a00 += e4.x*f4.x; a01 += e4.x*f4.y; a02 += e4.x*f4.z; a03 += e4.x*f4.w;
        a10 += e4.y*f4.x; a11 += e4.y*f4.y; a12 += e4.y*f4.z; a13 += e4.y*f4.w;
        a20 += e4.z*f4.x; a21 += e4.z*f4.y; a22 += e4.z*f4.z; a23 += e4.z*f4.w;
        a30 += e4.w*f4.x; a31 += e4.w*f4.y; a32 += e4.w*f4.z; a33 += e4.w*f4.w;
    }
    float* base = g_newcacc + c0*FE + f0;
    atomicAdd(base+0,      a00); atomicAdd(base+1,      a01);
    atomicAdd(base+2,      a02); atomicAdd(base+3,      a03);
    atomicAdd(base+FE+0,   a10); atomicAdd(base+FE+1,   a11);
    atomicAdd(base+FE+2,   a12); atomicAdd(base+FE+3,   a13);
    atomicAdd(base+2*FE+0, a20); atomicAdd(base+2*FE+1, a21);
    atomicAdd(base+2*FE+2, a22); atomicAdd(base+2*FE+3, a23);
    atomicAdd(base+3*FE+0, a30); atomicAdd(base+3*FE+1, a31);
    atomicAdd(base+3*FE+2, a32); atomicAdd(base+3*FE+3, a33);
}

// ------------------------- k5b: normalize + kv + M/d fold -------------------
__global__ __launch_bounds__(128) void k5b_kv(const float* __restrict__ kv_w,
                                              const float* __restrict__ kv_b,
                                              const float* __restrict__ qw,
                                              const float* __restrict__ qb) {
    int c = blockIdx.x;                          // grid 64
    int tid = threadIdx.x;
    __shared__ float nc_s[FE], k_s[FE];
    if (tid < FE) {
        float inv = 1.f / fmaxf(sqrtf(g_ssq[tid]), 1e-12f);
        nc_s[tid] = g_newcacc[c*FE + tid] * inv / g_colsum[c];
    }
    __syncthreads();
    {                                            // kv projection
        float a = kv_b[tid];
        const float* wr = kv_w + tid*FE;
#pragma unroll
        for (int f = 0; f < FE; f++) a += nc_s[f] * wr[f];
        if (tid < 64) k_s[tid] = a;
        else          g_v[c*FE + (tid - 64)] = a;
    }
    __syncthreads();
    if (tid < 64) {                              // M fold
        float m = 0.f;
#pragma unroll 8
        for (int j = 0; j < FE; j++) m += k_s[j] * qw[j*FE + tid];
        float inv = 1.f / fmaxf(sqrtf(g_ssq[tid]), 1e-12f);
        g_M[c*FE + tid] = 0.125f * inv * m;
    } else if (tid == 64) {                      // d fold
        float dd = 0.f;
        for (int j = 0; j < FE; j++) dd += qb[j] * k_s[j];
        g_d[c] = 0.125f * dd;
    }
}

// ------------------------- kAttn: logits -> softmax -> @v -> scatter --------
__global__ __launch_bounds__(64) void kAttn() {
    __shared__ float M_s[KK*FE];                  // 16 KB
    __shared__ float v_s[KK*FE];                  // 16 KB
    __shared__ float d_s[KK];
    int tid = threadIdx.x;
    for (int i = tid; i < KK*FE; i += 64) { M_s[i] = g_M[i]; v_s[i] = g_v[i]; }
    if (tid < KK) d_s[tid] = g_d[tid];
    __syncthreads();

    int n = blockIdx.x*64 + tid;                  // token id, grid NT/64
    float fr[FE];
    const float4* frp = reinterpret_cast<const float4*>(g_fea + n*FE);
#pragma unroll
    for (int f4 = 0; f4 < 16; f4++) {
        float4 v = frp[f4];
        fr[f4*4] = v.x; fr[f4*4+1] = v.y; fr[f4*4+2] = v.z; fr[f4*4+3] = v.w;
    }
    float a[KK];
    float mx = -1e30f;
#pragma unroll 4
    for (int c = 0; c < KK; c++) {
        const float4* mr = reinterpret_cast<const float4*>(M_s + c*FE);
        float l = d_s[c];
#pragma unroll
        for (int f4 = 0; f4 < 16; f4++) {
            float4 w = mr[f4];
            l += fr[f4*4]*w.x + fr[f4*4+1]*w.y + fr[f4*4+2]*w.z + fr[f4*4+3]*w.w;
        }
        a[c] = l;
        mx = fmaxf(mx, l);
    }
    float s = 0.f;
#pragma unroll
    for (int c = 0; c < KK; c++) { a[c] = __expf(a[c] - mx); s += a[c]; }
    float si = 1.f / s;

    float acc[FE];
#pragma unroll
    for (int f = 0; f < FE; f++) acc[f] = 0.f;
#pragma unroll 4
    for (int c = 0; c < KK; c++) {
        float ac = a[c] * si;
        const float4* vr = reinterpret_cast<const float4*>(v_s + c*FE);
#pragma unroll
        for (int f4 = 0; f4 < 16; f4++) {
            float4 v = vr[f4];
            acc[f4*4]   += ac*v.x; acc[f4*4+1] += ac*v.y;
            acc[f4*4+2] += ac*v.z; acc[f4*4+3] += ac*v.w;
        }
    }
    int xb = n & 31, yb = (n >> 5) & 31, zb = n >> 10;
#pragma unroll
    for (int f4 = 0; f4 < 16; f4++) {
        int pz = f4 >> 2, py = f4 & 3;
        int p = ((zb*4 + pz)*HH + (yb*4 + py))*WW + xb*4;
        *reinterpret_cast<float4*>(g_o1 + p) =
            make_float4(acc[f4*4], acc[f4*4+1], acc[f4*4+2], acc[f4*4+3]);
    }
}

// ------------------------- k9: upc conv + bias + residual (staged) ----------
#define K9_NV 256
__global__ __launch_bounds__(128) void k9_upc(const float* __restrict__ x,
                                              const float* __restrict__ uw,
                                              const float* __restrict__ ub,
                                              float* __restrict__ out) {
    __shared__ u64 w2[48*27];
    __shared__ float2 b2[48];
    __shared__ float xs[8][K9_NV + 4];
    __shared__ float os[8][K9_NV + 4];
    int tid = threadIdx.x;
    for (int i = tid; i < 48*27; i += 128) {
        int q = i / 27, t = i % 27;
        w2[i] = pk2(uw[(2*q)*27 + t], uw[(2*q+1)*27 + t]);
    }
    if (tid < 48) b2[tid] = make_float2(ub[2*tid], ub[2*tid+1]);

    int vbase = blockIdx.x * K9_NV;
    int pa = vbase + tid, pb = vbase + 128 + tid;

    u64 oa[27], ob[27];
    {
        int za = pa >> 14, ya = (pa >> 7) & 127, xa = pa & 127;
        int zb = pb >> 14, yb = (pb >> 7) & 127, xb = pb & 127;
#pragma unroll
        for (int kz = 0; kz < 3; kz++)
#pragma unroll
        for (int ky = 0; ky < 3; ky++)
#pragma unroll
        for (int kx = 0; kx < 3; kx++) {
            int t = kz*9 + ky*3 + kx;
            int zz = za + kz - 1, yy = ya + ky - 1, xc = xa + kx - 1;
            float v = 0.f;
            if ((unsigned)zz < DD && (unsigned)yy < HH && (unsigned)xc < WW)
                v = g_o1[(zz*HH + yy)*WW + xc];
            oa[t] = pk2(v, v);
            zz = zb + kz - 1; yy = yb + ky - 1; xc = xb + kx - 1;
            v = 0.f;
            if ((unsigned)zz < DD && (unsigned)yy < HH && (unsigned)xc < WW)
                v = g_o1[(zz*HH + yy)*WW + xc];
            ob[t] = pk2(v, v);
        }
    }

    for (int cb = 0; cb < CC; cb += 8) {
        __syncthreads();
#pragma unroll
        for (int it = 0; it < 4; it++) {          // stage x slab, coalesced
            int e = it*128 + tid;
            int v = e >> 1, slot = e & 1;
            float4 val = *reinterpret_cast<const float4*>(
                x + (size_t)(vbase + v)*CC + cb + slot*4);
            xs[slot*4+0][v] = val.x; xs[slot*4+1][v] = val.y;
            xs[slot*4+2][v] = val.z; xs[slot*4+3][v] = val.w;
        }
        __syncthreads();
#pragma unroll
        for (int q = 0; q < 4; q++) {             // channel pair cb+2q, cb+2q+1
            float2 bb = b2[cb/2 + q];
            u64 acc_a = pk2(xs[2*q][tid]     + bb.x, xs[2*q+1][tid]     + bb.y);
            u64 acc_b = pk2(xs[2*q][128+tid] + bb.x, xs[2*q+1][128+tid] + bb.y);
            const u64* wr = w2 + (cb/2 + q)*27;
#pragma unroll
            for (int t = 0; t < 27; t++) {
                u64 w = wr[t];
                acc_a = ffma2(oa[t], w, acc_a);
                acc_b = ffma2(ob[t], w, acc_b);
            }
            float2 ra = upk2(acc_a), rb = upk2(acc_b);
            os[2*q][tid]     = ra.x; os[2*q+1][tid]     = ra.y;
            os[2*q][128+tid] = rb.x; os[2*q+1][128+tid] = rb.y;
        }
        __syncthreads();
#pragma unroll
        for (int it = 0; it < 4; it++) {          // drain out slab, coalesced
            int e = it*128 + tid;
            int v = e >> 1, slot = e & 1;
            float4 val = make_float4(os[slot*4+0][v], os[slot*4+1][v],
                                     os[slot*4+2][v], os[slot*4+3][v]);
            *reinterpret_cast<float4*>(
                out + (size_t)(vbase + v)*CC + cb + slot*4) = val;
        }
    }
}

// ------------------------- launch --------------------------------------------
extern "C" void kernel_launch(void* const* d_in, const int* in_sizes, int n_in,
                              void* d_out, int out_size) {
    const float* x     = (const float*)d_in[0];
    const float* cen   = (const float*)d_in[1];
    const float* dwc_w = (const float*)d_in[2];
    const float* dwc_b = (const float*)d_in[3];
    const float* upc_w = (const float*)d_in[4];
    const float* upc_b = (const float*)d_in[5];
    const float* q_w   = (const float*)d_in[6];
    const float* q_b   = (const float*)d_in[7];
    const float* kv_w  = (const float*)d_in[8];
    const float* kv_b  = (const float*)d_in[9];
    float* out = (float*)d_out;

    init0     <<<1, 128>>>();
    init1     <<<1, 256>>>();
    init2     <<<1, 256>>>();
    k1_dwc1   <<<K1_GRID, 128>>>(x, dwc_w);     // 4th launch -> ncu profiles this
    k2_gather <<<NP/256, 256>>>(dwc_b);
    k4b_logits<<<(NT*4)/256, 256>>>(cen);
    k5a_gemm  <<<NT/32, 256>>>();
    k5b_kv    <<<KK, 128>>>(kv_w, kv_b, q_w, q_b);
    kAttn     <<<NT/64, 64>>>();
    k9_upc    <<<NP/K9_NV, 128>>>(x, upc_w, upc_b, out);
}

// round 10
// speedup vs baseline: 1.1624x; 1.1624x over previous
#include <cuda_runtime.h>
#include <cuda_bf16.h>
#include <math.h>
#include <cstdint>

// ---------------------------------------------------------------------------
// ClusterAttn: b=1, D=32, H=128, W=128, C=96, P=4, FEAD=64, K=64
//  init0/1/2 : zero small accumulators (keeps k1 as ncu's 4th launch)
//  k1_mma    : dwc stage1 via mma.sync (HMMA bf16): Y[NP,27] = X[NP,96]@W[96,27]
//  k2        : 27-tap gather -> fea (raw) + column sum-of-squares
//  k4b       : soft-assign logits (inv folded into centroids) -> expl + colsum
//  k5a       : newcacc = E^T @ fea  (32-token tiles, 256 blocks, atomics)
//  k5b       : normalize -> kv -> fold M/d
//  kAttn     : logits -> softmax -> attn@v -> scatter to o1
//  k9        : upc conv (1->96) + bias + residual x
// ---------------------------------------------------------------------------

#define DD 32
#define HH 128
#define WW 128
#define NP (DD*HH*WW)      // 524288 voxels
#define CC 96
#define NT 8192            // tokens
#define FE 64              // FEAD
#define KK 64              // clusters

// ------------------------- scratch (device globals) -------------------------
__device__ __align__(256) __nv_bfloat16 g_yb[27*NP];   // 28.3 MB
__device__ __align__(256) float g_fea[NT*FE];          // raw (un-normalized)
__device__ __align__(256) float g_expl[NT*KK];
__device__ __align__(256) float g_o1[NP];
__device__ __align__(256) float g_ssq[FE];
__device__ __align__(256) float g_colsum[KK];
__device__ __align__(256) float g_newcacc[KK*FE];
__device__ __align__(256) float g_v[KK*FE];
__device__ __align__(256) float g_M[KK*FE];
__device__ __align__(256) float g_d[KK];

// ------------------------- f32x2 packed helpers -----------------------------
using u64 = unsigned long long;
__device__ __forceinline__ u64 pk2(float a, float b) {
    u64 r; asm("mov.b64 %0,{%1,%2};" : "=l"(r) : "f"(a), "f"(b)); return r;
}
__device__ __forceinline__ float2 upk2(u64 v) {
    float2 r; asm("mov.b64 {%0,%1},%2;" : "=f"(r.x), "=f"(r.y) : "l"(v)); return r;
}
__device__ __forceinline__ u64 ffma2(u64 a, u64 b, u64 c) {
    u64 d; asm("fma.rn.f32x2 %0,%1,%2,%3;" : "=l"(d) : "l"(a), "l"(b), "l"(c)); return d;
}

// ------------------------- warp-level bf16 MMA -------------------------------
__device__ __forceinline__ void mma16816(float* c,
        uint32_t a0, uint32_t a1, uint32_t a2, uint32_t a3,
        uint32_t b0, uint32_t b1) {
    asm volatile(
        "mma.sync.aligned.m16n8k16.row.col.f32.bf16.bf16.f32 "
        "{%0,%1,%2,%3}, {%4,%5,%6,%7}, {%8,%9}, {%0,%1,%2,%3};"
        : "+f"(c[0]), "+f"(c[1]), "+f"(c[2]), "+f"(c[3])
        : "r"(a0), "r"(a1), "r"(a2), "r"(a3), "r"(b0), "r"(b1));
}

// ------------------------- init kernels (launch-order shims) ----------------
__global__ void init0() {
    int t = threadIdx.x;
    if (t < FE) g_ssq[t] = 0.f;
    if (t < KK) g_colsum[t] = 0.f;
}
__global__ void init1() {
    int t = threadIdx.x;
    for (int i = t; i < KK*FE/2; i += 256) g_newcacc[i] = 0.f;
}
__global__ void init2() {
    int t = threadIdx.x;
    for (int i = t; i < KK*FE/2; i += 256) g_newcacc[KK*FE/2 + i] = 0.f;
}

// ------------------------- k1: dwc stage1 via mma.sync -----------------------
// Block 128 threads / 512 voxels (4 subtiles of 128). Per warp: 32 voxels =
// two m16n8k16 tiles x 4 n-tiles x 6 k-steps. A = x rows bf16 (smem, stride-52
// pad: conflict-free for fragment gather), B = dwc_w bf16 (stride-40 pad).
// Taps 27..31 and the K=96..127 tail are zero / skipped.
#define K1_VB 512
__global__ __launch_bounds__(128) void k1_mma(const float* __restrict__ x,
                                              const float* __restrict__ dwc_w) {
    __shared__ uint32_t ws[48*40];       // B: bf16x2 (W[2m][n], W[2m+1][n])
    __shared__ uint32_t xs[128*52];      // A: bf16x2 (x[v][2m], x[v][2m+1])
    __shared__ float    os[27*128];      // D transpose buffer
    int tid = threadIdx.x, lane = tid & 31, wid = tid >> 5;
    int g = lane >> 2, tg = lane & 3;

    for (int i = tid; i < 48*32; i += 128) {
        int m = i >> 5, n = i & 31;
        float w0 = 0.f, w1 = 0.f;
        if (n < 27) { w0 = dwc_w[(2*m)*27 + n]; w1 = dwc_w[(2*m+1)*27 + n]; }
        __nv_bfloat162 h = __floats2bfloat162_rn(w0, w1);
        ws[m*40 + n] = *reinterpret_cast<uint32_t*>(&h);
    }

    int vbase = blockIdx.x * K1_VB;
#pragma unroll 1
    for (int sub = 0; sub < 4; sub++) {
        int v0 = vbase + sub*128;
        __syncthreads();                 // prev pack-store (os reads) done
        // stage 128 vox x 96 ch as bf16x2, coalesced float4 reads
        const float4* src = reinterpret_cast<const float4*>(x + (size_t)v0*CC);
#pragma unroll
        for (int it = 0; it < 24; it++) {
            int e = it*128 + tid;
            float4 val = src[e];
            int v = e / 24, c4 = e % 24;
            __nv_bfloat162 h0 = __floats2bfloat162_rn(val.x, val.y);
            __nv_bfloat162 h1 = __floats2bfloat162_rn(val.z, val.w);
            xs[v*52 + c4*2]     = *reinterpret_cast<uint32_t*>(&h0);
            xs[v*52 + c4*2 + 1] = *reinterpret_cast<uint32_t*>(&h1);
        }
        __syncthreads();

        float c[2][4][4];
#pragma unroll
        for (int tl = 0; tl < 2; tl++)
#pragma unroll
            for (int nt = 0; nt < 4; nt++)
#pragma unroll
                for (int j = 0; j < 4; j++) c[tl][nt][j] = 0.f;

#pragma unroll
        for (int tl = 0; tl < 2; tl++) {
            int vloc = wid*32 + tl*16 + g;
#pragma unroll
            for (int ks = 0; ks < 6; ks++) {
                int m0 = ks*8 + tg;
                uint32_t a0 = xs[vloc*52 + m0];
                uint32_t a1 = xs[(vloc+8)*52 + m0];
                uint32_t a2 = xs[vloc*52 + m0 + 4];
                uint32_t a3 = xs[(vloc+8)*52 + m0 + 4];
#pragma unroll
                for (int nt = 0; nt < 4; nt++) {
                    uint32_t b0 = ws[(ks*8 + tg)*40     + nt*8 + g];
                    uint32_t b1 = ws[(ks*8 + tg + 4)*40 + nt*8 + g];
                    mma16816(c[tl][nt], a0, a1, a2, a3, b0, b1);
                }
            }
        }
        // scatter D fragments into os[tap][voxel]
#pragma unroll
        for (int tl = 0; tl < 2; tl++) {
            int row = wid*32 + tl*16 + g;
#pragma unroll
            for (int nt = 0; nt < 4; nt++) {
                int col = nt*8 + tg*2;
                if (col < 27) {
                    os[col*128 + row]     = c[tl][nt][0];
                    os[col*128 + row + 8] = c[tl][nt][2];
                }
                if (col + 1 < 27) {
                    os[(col+1)*128 + row]     = c[tl][nt][1];
                    os[(col+1)*128 + row + 8] = c[tl][nt][3];
                }
            }
        }
        __syncthreads();
        // pack bf16x2 + coalesced store per tap row
        for (int i = tid; i < 27*64; i += 128) {
            int t = i >> 6, p = i & 63;
            __nv_bfloat162 h = __floats2bfloat162_rn(os[t*128 + 2*p],
                                                     os[t*128 + 2*p + 1]);
            *reinterpret_cast<uint32_t*>(
                reinterpret_cast<char*>(g_yb) + ((size_t)t*NP + v0 + 2*p)*2) =
                *reinterpret_cast<uint32_t*>(&h);
        }
    }
}

// ------------------------- k2: gather + fea (raw) + ssq ----------------------
__global__ __launch_bounds__(256) void k2_gather(const float* __restrict__ dwc_b) {
    __shared__ float ssq_s[FE];
    int tid = threadIdx.x;
    if (tid < FE) ssq_s[tid] = 0.f;
    __syncthreads();

    int p = blockIdx.x*256 + tid;
    int z = p >> 14, y = (p >> 7) & 127, xx = p & 127;

    float v = dwc_b[0];
#pragma unroll
    for (int kz = 0; kz < 3; kz++) {
        int zz = z + kz - 1; if ((unsigned)zz >= DD) continue;
#pragma unroll
        for (int ky = 0; ky < 3; ky++) {
            int yy = y + ky - 1; if ((unsigned)yy >= HH) continue;
#pragma unroll
            for (int kx = 0; kx < 3; kx++) {
                int xc = xx + kx - 1; if ((unsigned)xc >= WW) continue;
                int t = kz*9 + ky*3 + kx;
                v += __bfloat162float(g_yb[(size_t)t*NP + (zz*HH + yy)*WW + xc]);
            }
        }
    }
    int n = ((z >> 2) << 10) | ((y >> 2) << 5) | (xx >> 2);
    int f = ((z & 3) << 4) | ((y & 3) << 2) | (xx & 3);
    g_fea[n*FE + f] = v;
    atomicAdd(&ssq_s[f], v*v);
    __syncthreads();
    if (tid < FE) atomicAdd(&g_ssq[tid], ssq_s[tid]);
}

// ------------------------- k4b: soft-assign logits + exp + colsum -----------
__global__ __launch_bounds__(256) void k4b_logits(const float* __restrict__ cen) {
    __shared__ float4 cen_s[KK*16];
    __shared__ float inv_s[FE];
    __shared__ float cs_s[KK];
    int tid = threadIdx.x;
    if (tid < FE) inv_s[tid] = 1.f / fmaxf(sqrtf(g_ssq[tid]), 1e-12f);
    if (tid < KK) cs_s[tid] = 0.f;
    __syncthreads();
    for (int i = tid; i < KK*16; i += 256) {
        float4 w = reinterpret_cast<const float4*>(cen)[i];
        int f0 = (i*4) & 63;
        w.x *= inv_s[f0]; w.y *= inv_s[f0+1]; w.z *= inv_s[f0+2]; w.w *= inv_s[f0+3];
        cen_s[i] = w;
    }
    __syncthreads();

    int idx = blockIdx.x*256 + tid;              // (n, c-quarter)
    int n = idx >> 2, c0 = (idx & 3) * 16;
    float fr[FE];
    const float4* frp = reinterpret_cast<const float4*>(g_fea + n*FE);
#pragma unroll
    for (int f4 = 0; f4 < 16; f4++) {
        float4 v = frp[f4];
        fr[f4*4] = v.x; fr[f4*4+1] = v.y; fr[f4*4+2] = v.z; fr[f4*4+3] = v.w;
    }
#pragma unroll
    for (int cc = 0; cc < 16; cc++) {
        int c = c0 + cc;
        const float4* cr = cen_s + c*16;
        float l = 0.f;
#pragma unroll
        for (int f4 = 0; f4 < 16; f4++) {
            float4 w = cr[f4];
            l += fr[f4*4]*w.x + fr[f4*4+1]*w.y + fr[f4*4+2]*w.z + fr[f4*4+3]*w.w;
        }
        float e = __expf(l);
        g_expl[n*KK + c] = e;
        atomicAdd(&cs_s[c], e);
    }
    __syncthreads();
    if (tid < KK) atomicAdd(&g_colsum[tid], cs_s[tid]);
}

// ------------------------- k5a: newcacc = E^T @ fea (tiled GEMM) ------------
__global__ __launch_bounds__(256) void k5a_gemm() {
    __shared__ float e_s[32][68];
    __shared__ float f_s[32][68];
    int tid = threadIdx.x;
    int n0 = blockIdx.x * 32;
#pragma unroll
    for (int k = 0; k < 8; k++) {
        int idx = k*256 + tid;
        int r = idx >> 6, c = idx & 63;
        e_s[r][c] = g_expl[(n0 + r)*KK + c];
        f_s[r][c] = g_fea [(n0 + r)*FE + c];
    }
    __syncthreads();

    int c0 = (tid >> 4) * 4;
    int f0 = (tid & 15) * 4;
    float a00=0,a01=0,a02=0,a03=0, a10=0,a11=0,a12=0,a13=0;
    float a20=0,a21=0,a22=0,a23=0, a30=0,a31=0,a32=0,a33=0;
#pragma unroll 8
    for (int n = 0; n < 32; n++) {
        float4 e4 = *reinterpret_cast<const float4*>(&e_s[n][c0]);
        float4 f4 = *reinterpret_cast<const float4*>(&f_s[n][f0]);
        a00 += e4.x*f4.x; a01 += e4.x*f4.y; a02 += e4.x*f4.z; a03 += e4.x*f4.w;
        a10 += e4.y*f4.x; a11 += e4.y*f4.y; a12 += e4.y*f4.z; a13 += e4.y*f4.w;
        a20 += e4.z*f4.x; a21 += e4.z*f4.y; a22 += e4.z*f4.z; a23 += e4.z*f4.w;
        a30 += e4.w*f4.x; a31 += e4.w*f4.y; a32 += e4.w*f4.z; a33 += e4.w*f4.w;
    }
    float* base = g_newcacc + c0*FE + f0;
    atomicAdd(base+0,      a00); atomicAdd(base+1,      a01);
    atomicAdd(base+2,      a02); atomicAdd(base+3,      a03);
    atomicAdd(base+FE+0,   a10); atomicAdd(base+FE+1,   a11);
    atomicAdd(base+FE+2,   a12); atomicAdd(base+FE+3,   a13);
    atomicAdd(base+2*FE+0, a20); atomicAdd(base+2*FE+1, a21);
    atomicAdd(base+2*FE+2, a22); atomicAdd(base+2*FE+3, a23);
    atomicAdd(base+3*FE+0, a30); atomicAdd(base+3*FE+1, a31);
    atomicAdd(base+3*FE+2, a32); atomicAdd(base+3*FE+3, a33);
}

// ------------------------- k5b: normalize + kv + M/d fold -------------------
__global__ __launch_bounds__(128) void k5b_kv(const float* __restrict__ kv_w,
                                              const float* __restrict__ kv_b,
                                              const float* __restrict__ qw,
                                              const float* __restrict__ qb) {
    int c = blockIdx.x;                          // grid 64
    int tid = threadIdx.x;
    __shared__ float nc_s[FE], k_s[FE];
    if (tid < FE) {
        float inv = 1.f / fmaxf(sqrtf(g_ssq[tid]), 1e-12f);
        nc_s[tid] = g_newcacc[c*FE + tid] * inv / g_colsum[c];
    }
    __syncthreads();
    {                                            // kv projection
        float a = kv_b[tid];
        const float* wr = kv_w + tid*FE;
#pragma unroll
        for (int f = 0; f < FE; f++) a += nc_s[f] * wr[f];
        if (tid < 64) k_s[tid] = a;
        else          g_v[c*FE + (tid - 64)] = a;
    }
    __syncthreads();
    if (tid < 64) {                              // M fold
        float m = 0.f;
#pragma unroll 8
        for (int j = 0; j < FE; j++) m += k_s[j] * qw[j*FE + tid];
        float inv = 1.f / fmaxf(sqrtf(g_ssq[tid]), 1e-12f);
        g_M[c*FE + tid] = 0.125f * inv * m;
    } else if (tid == 64) {                      // d fold
        float dd = 0.f;
        for (int j = 0; j < FE; j++) dd += qb[j] * k_s[j];
        g_d[c] = 0.125f * dd;
    }
}

// ------------------------- kAttn: logits -> softmax -> @v -> scatter --------
__global__ __launch_bounds__(64) void kAttn() {
    __shared__ float M_s[KK*FE];                  // 16 KB
    __shared__ float v_s[KK*FE];                  // 16 KB
    __shared__ float d_s[KK];
    int tid = threadIdx.x;
    for (int i = tid; i < KK*FE; i += 64) { M_s[i] = g_M[i]; v_s[i] = g_v[i]; }
    if (tid < KK) d_s[tid] = g_d[tid];
    __syncthreads();

    int n = blockIdx.x*64 + tid;                  // token id, grid NT/64
    float fr[FE];
    const float4* frp = reinterpret_cast<const float4*>(g_fea + n*FE);
#pragma unroll
    for (int f4 = 0; f4 < 16; f4++) {
        float4 v = frp[f4];
        fr[f4*4] = v.x; fr[f4*4+1] = v.y; fr[f4*4+2] = v.z; fr[f4*4+3] = v.w;
    }
    float a[KK];
    float mx = -1e30f;
#pragma unroll 4
    for (int c = 0; c < KK; c++) {
        const float4* mr = reinterpret_cast<const float4*>(M_s + c*FE);
        float l = d_s[c];
#pragma unroll
        for (int f4 = 0; f4 < 16; f4++) {
            float4 w = mr[f4];
            l += fr[f4*4]*w.x + fr[f4*4+1]*w.y + fr[f4*4+2]*w.z + fr[f4*4+3]*w.w;
        }
        a[c] = l;
        mx = fmaxf(mx, l);
    }
    float s = 0.f;
#pragma unroll
    for (int c = 0; c < KK; c++) { a[c] = __expf(a[c] - mx); s += a[c]; }
    float si = 1.f / s;

    float acc[FE];
#pragma unroll
    for (int f = 0; f < FE; f++) acc[f] = 0.f;
#pragma unroll 4
    for (int c = 0; c < KK; c++) {
        float ac = a[c] * si;
        const float4* vr = reinterpret_cast<const float4*>(v_s + c*FE);
#pragma unroll
        for (int f4 = 0; f4 < 16; f4++) {
            float4 v = vr[f4];
            acc[f4*4]   += ac*v.x; acc[f4*4+1] += ac*v.y;
            acc[f4*4+2] += ac*v.z; acc[f4*4+3] += ac*v.w;
        }
    }
    int xb = n & 31, yb = (n >> 5) & 31, zb = n >> 10;
#pragma unroll
    for (int f4 = 0; f4 < 16; f4++) {
        int pz = f4 >> 2, py = f4 & 3;
        int p = ((zb*4 + pz)*HH + (yb*4 + py))*WW + xb*4;
        *reinterpret_cast<float4*>(g_o1 + p) =
            make_float4(acc[f4*4], acc[f4*4+1], acc[f4*4+2], acc[f4*4+3]);
    }
}

// ------------------------- k9: upc conv + bias + residual (staged) ----------
#define K9_NV 256
__global__ __launch_bounds__(128) void k9_upc(const float* __restrict__ x,
                                              const float* __restrict__ uw,
                                              const float* __restrict__ ub,
                                              float* __restrict__ out) {
    __shared__ u64 w2[48*27];
    __shared__ float2 b2[48];
    __shared__ float xs[8][K9_NV + 4];
    __shared__ float os[8][K9_NV + 4];
    int tid = threadIdx.x;
    for (int i = tid; i < 48*27; i += 128) {
        int q = i / 27, t = i % 27;
        w2[i] = pk2(uw[(2*q)*27 + t], uw[(2*q+1)*27 + t]);
    }
    if (tid < 48) b2[tid] = make_float2(ub[2*tid], ub[2*tid+1]);

    int vbase = blockIdx.x * K9_NV;
    int pa = vbase + tid, pb = vbase + 128 + tid;

    u64 oa[27], ob[27];
    {
        int za = pa >> 14, ya = (pa >> 7) & 127, xa = pa & 127;
        int zb = pb >> 14, yb = (pb >> 7) & 127, xb = pb & 127;
#pragma unroll
        for (int kz = 0; kz < 3; kz++)
#pragma unroll
        for (int ky = 0; ky < 3; ky++)
#pragma unroll
        for (int kx = 0; kx < 3; kx++) {
            int t = kz*9 + ky*3 + kx;
            int zz = za + kz - 1, yy = ya + ky - 1, xc = xa + kx - 1;
            float v = 0.f;
            if ((unsigned)zz < DD && (unsigned)yy < HH && (unsigned)xc < WW)
                v = g_o1[(zz*HH + yy)*WW + xc];
            oa[t] = pk2(v, v);
            zz = zb + kz - 1; yy = yb + ky - 1; xc = xb + kx - 1;
            v = 0.f;
            if ((unsigned)zz < DD && (unsigned)yy < HH && (unsigned)xc < WW)
                v = g_o1[(zz*HH + yy)*WW + xc];
            ob[t] = pk2(v, v);
        }
    }

    for (int cb = 0; cb < CC; cb += 8) {
        __syncthreads();
#pragma unroll
        for (int it = 0; it < 4; it++) {          // stage x slab, coalesced
            int e = it*128 + tid;
            int v = e >> 1, slot = e & 1;
            float4 val = *reinterpret_cast<const float4*>(
                x + (size_t)(vbase + v)*CC + cb + slot*4);
            xs[slot*4+0][v] = val.x; xs[slot*4+1][v] = val.y;
            xs[slot*4+2][v] = val.z; xs[slot*4+3][v] = val.w;
        }
        __syncthreads();
#pragma unroll
        for (int q = 0; q < 4; q++) {             // channel pair cb+2q, cb+2q+1
            float2 bb = b2[cb/2 + q];
            u64 acc_a = pk2(xs[2*q][tid]     + bb.x, xs[2*q+1][tid]     + bb.y);
            u64 acc_b = pk2(xs[2*q][128+tid] + bb.x, xs[2*q+1][128+tid] + bb.y);
            const u64* wr = w2 + (cb/2 + q)*27;
#pragma unroll
            for (int t = 0; t < 27; t++) {
                u64 w = wr[t];
                acc_a = ffma2(oa[t], w, acc_a);
                acc_b = ffma2(ob[t], w, acc_b);
            }
            float2 ra = upk2(acc_a), rb = upk2(acc_b);
            os[2*q][tid]     = ra.x; os[2*q+1][tid]     = ra.y;
            os[2*q][128+tid] = rb.x; os[2*q+1][128+tid] = rb.y;
        }
        __syncthreads();
#pragma unroll
        for (int it = 0; it < 4; it++) {          // drain out slab, coalesced
            int e = it*128 + tid;
            int v = e >> 1, slot = e & 1;
            float4 val = make_float4(os[slot*4+0][v], os[slot*4+1][v],
                                     os[slot*4+2][v], os[slot*4+3][v]);
            *reinterpret_cast<float4*>(
                out + (size_t)(vbase + v)*CC + cb + slot*4) = val;
        }
    }
}

// ------------------------- launch --------------------------------------------
extern "C" void kernel_launch(void* const* d_in, const int* in_sizes, int n_in,
                              void* d_out, int out_size) {
    const float* x     = (const float*)d_in[0];
    const float* cen   = (const float*)d_in[1];
    const float* dwc_w = (const float*)d_in[2];
    const float* dwc_b = (const float*)d_in[3];
    const float* upc_w = (const float*)d_in[4];
    const float* upc_b = (const float*)d_in[5];
    const float* q_w   = (const float*)d_in[6];
    const float* q_b   = (const float*)d_in[7];
    const float* kv_w  = (const float*)d_in[8];
    const float* kv_b  = (const float*)d_in[9];
    float* out = (float*)d_out;

    init0     <<<1, 128>>>();
    init1     <<<1, 256>>>();
    init2     <<<1, 256>>>();
    k1_mma    <<<NP/K1_VB, 128>>>(x, dwc_w);    // 4th launch -> ncu profiles this
    k2_gather <<<NP/256, 256>>>(dwc_b);
    k4b_logits<<<(NT*4)/256, 256>>>(cen);
    k5a_gemm  <<<NT/32, 256>>>();
    k5b_kv    <<<KK, 128>>>(kv_w, kv_b, q_w, q_b);
    kAttn     <<<NT/64, 64>>>();
    k9_upc    <<<NP/K9_NV, 128>>>(x, upc_w, upc_b, out);
}

// round 11
// speedup vs baseline: 1.3398x; 1.1526x over previous
#include <cuda_runtime.h>
#include <cuda_bf16.h>
#include <math.h>
#include <cstdint>

// ---------------------------------------------------------------------------
// ClusterAttn: b=1, D=32, H=128, W=128, C=96, P=4, FEAD=64, K=64
//  init0/init12 : zero small accumulators (keeps k2 as ncu's 4th launch)
//  k1_mma : dwc stage1 via mma.sync bf16: Y[NP,27] = X[NP,96]@W[96,27]
//  k2     : 27-tap gather -> fea (raw) + column sum-of-squares   [profiled]
//  k4b    : soft-assign logits (inv folded into centroids) -> expl + colsum
//  k5a    : newcacc = E^T @ fea  (32-token tiles, 256 blocks, atomics)
//  k5b    : normalize -> kv -> fold M/d
//  kAttn  : logits -> softmax -> attn@v -> scatter to o1
//  k9_mma : upc conv as GEMM via mma.sync: OUT = O1taps[NP,27]@W[27,96]+x+b
// ---------------------------------------------------------------------------

#define DD 32
#define HH 128
#define WW 128
#define NP (DD*HH*WW)      // 524288 voxels
#define CC 96
#define NT 8192            // tokens
#define FE 64              // FEAD
#define KK 64              // clusters

// ------------------------- scratch (device globals) -------------------------
__device__ __align__(256) __nv_bfloat16 g_yb[27*NP];   // 28.3 MB
__device__ __align__(256) float g_fea[NT*FE];          // raw (un-normalized)
__device__ __align__(256) float g_expl[NT*KK];
__device__ __align__(256) float g_o1[NP];
__device__ __align__(256) float g_ssq[FE];
__device__ __align__(256) float g_colsum[KK];
__device__ __align__(256) float g_newcacc[KK*FE];
__device__ __align__(256) float g_v[KK*FE];
__device__ __align__(256) float g_M[KK*FE];
__device__ __align__(256) float g_d[KK];

// ------------------------- warp-level bf16 MMA -------------------------------
__device__ __forceinline__ void mma16816(float* c,
        uint32_t a0, uint32_t a1, uint32_t a2, uint32_t a3,
        uint32_t b0, uint32_t b1) {
    asm volatile(
        "mma.sync.aligned.m16n8k16.row.col.f32.bf16.bf16.f32 "
        "{%0,%1,%2,%3}, {%4,%5,%6,%7}, {%8,%9}, {%0,%1,%2,%3};"
        : "+f"(c[0]), "+f"(c[1]), "+f"(c[2]), "+f"(c[3])
        : "r"(a0), "r"(a1), "r"(a2), "r"(a3), "r"(b0), "r"(b1));
}

// ------------------------- init kernels (launch-order shims) ----------------
__global__ void init0() {
    int t = threadIdx.x;
    if (t < FE) g_ssq[t] = 0.f;
    if (t < KK) g_colsum[t] = 0.f;
}
__global__ void init12() {
    int t = threadIdx.x;
    for (int i = t; i < KK*FE; i += 256) g_newcacc[i] = 0.f;
}

// ------------------------- k1: dwc stage1 via mma.sync -----------------------
#define K1_VB 512
__global__ __launch_bounds__(128) void k1_mma(const float* __restrict__ x,
                                              const float* __restrict__ dwc_w) {
    __shared__ uint32_t ws[48*40];       // B: bf16x2 (W[2m][n], W[2m+1][n])
    __shared__ uint32_t xs[128*52];      // A: bf16x2 (x[v][2m], x[v][2m+1])
    __shared__ float    os[27*128];      // D transpose buffer
    int tid = threadIdx.x, lane = tid & 31, wid = tid >> 5;
    int g = lane >> 2, tg = lane & 3;

    for (int i = tid; i < 48*32; i += 128) {
        int m = i >> 5, n = i & 31;
        float w0 = 0.f, w1 = 0.f;
        if (n < 27) { w0 = dwc_w[(2*m)*27 + n]; w1 = dwc_w[(2*m+1)*27 + n]; }
        __nv_bfloat162 h = __floats2bfloat162_rn(w0, w1);
        ws[m*40 + n] = *reinterpret_cast<uint32_t*>(&h);
    }

    int vbase = blockIdx.x * K1_VB;
#pragma unroll 1
    for (int sub = 0; sub < 4; sub++) {
        int v0 = vbase + sub*128;
        __syncthreads();
        const float4* src = reinterpret_cast<const float4*>(x + (size_t)v0*CC);
#pragma unroll
        for (int it = 0; it < 24; it++) {
            int e = it*128 + tid;
            float4 val = src[e];
            int v = e / 24, c4 = e % 24;
            __nv_bfloat162 h0 = __floats2bfloat162_rn(val.x, val.y);
            __nv_bfloat162 h1 = __floats2bfloat162_rn(val.z, val.w);
            xs[v*52 + c4*2]     = *reinterpret_cast<uint32_t*>(&h0);
            xs[v*52 + c4*2 + 1] = *reinterpret_cast<uint32_t*>(&h1);
        }
        __syncthreads();

        float c[2][4][4];
#pragma unroll
        for (int tl = 0; tl < 2; tl++)
#pragma unroll
            for (int nt = 0; nt < 4; nt++)
#pragma unroll
                for (int j = 0; j < 4; j++) c[tl][nt][j] = 0.f;

#pragma unroll
        for (int tl = 0; tl < 2; tl++) {
            int vloc = wid*32 + tl*16 + g;
#pragma unroll
            for (int ks = 0; ks < 6; ks++) {
                int m0 = ks*8 + tg;
                uint32_t a0 = xs[vloc*52 + m0];
                uint32_t a1 = xs[(vloc+8)*52 + m0];
                uint32_t a2 = xs[vloc*52 + m0 + 4];
                uint32_t a3 = xs[(vloc+8)*52 + m0 + 4];
#pragma unroll
                for (int nt = 0; nt < 4; nt++) {
                    uint32_t b0 = ws[(ks*8 + tg)*40     + nt*8 + g];
                    uint32_t b1 = ws[(ks*8 + tg + 4)*40 + nt*8 + g];
                    mma16816(c[tl][nt], a0, a1, a2, a3, b0, b1);
                }
            }
        }
#pragma unroll
        for (int tl = 0; tl < 2; tl++) {
            int row = wid*32 + tl*16 + g;
#pragma unroll
            for (int nt = 0; nt < 4; nt++) {
                int col = nt*8 + tg*2;
                if (col < 27) {
                    os[col*128 + row]     = c[tl][nt][0];
                    os[col*128 + row + 8] = c[tl][nt][2];
                }
                if (col + 1 < 27) {
                    os[(col+1)*128 + row]     = c[tl][nt][1];
                    os[(col+1)*128 + row + 8] = c[tl][nt][3];
                }
            }
        }
        __syncthreads();
        for (int i = tid; i < 27*64; i += 128) {
            int t = i >> 6, p = i & 63;
            __nv_bfloat162 h = __floats2bfloat162_rn(os[t*128 + 2*p],
                                                     os[t*128 + 2*p + 1]);
            *reinterpret_cast<uint32_t*>(
                reinterpret_cast<char*>(g_yb) + ((size_t)t*NP + v0 + 2*p)*2) =
                *reinterpret_cast<uint32_t*>(&h);
        }
    }
}

// ------------------------- k2: gather + fea (raw) + ssq ----------------------
__global__ __launch_bounds__(256) void k2_gather(const float* __restrict__ dwc_b) {
    __shared__ float ssq_s[FE];
    int tid = threadIdx.x;
    if (tid < FE) ssq_s[tid] = 0.f;
    __syncthreads();

    int p = blockIdx.x*256 + tid;
    int z = p >> 14, y = (p >> 7) & 127, xx = p & 127;

    float v = dwc_b[0];
#pragma unroll
    for (int kz = 0; kz < 3; kz++) {
        int zz = z + kz - 1; if ((unsigned)zz >= DD) continue;
#pragma unroll
        for (int ky = 0; ky < 3; ky++) {
            int yy = y + ky - 1; if ((unsigned)yy >= HH) continue;
#pragma unroll
            for (int kx = 0; kx < 3; kx++) {
                int xc = xx + kx - 1; if ((unsigned)xc >= WW) continue;
                int t = kz*9 + ky*3 + kx;
                v += __bfloat162float(g_yb[(size_t)t*NP + (zz*HH + yy)*WW + xc]);
            }
        }
    }
    int n = ((z >> 2) << 10) | ((y >> 2) << 5) | (xx >> 2);
    int f = ((z & 3) << 4) | ((y & 3) << 2) | (xx & 3);
    g_fea[n*FE + f] = v;
    atomicAdd(&ssq_s[f], v*v);
    __syncthreads();
    if (tid < FE) atomicAdd(&g_ssq[tid], ssq_s[tid]);
}

// ------------------------- k4b: soft-assign logits + exp + colsum -----------
__global__ __launch_bounds__(256) void k4b_logits(const float* __restrict__ cen) {
    __shared__ float4 cen_s[KK*16];
    __shared__ float inv_s[FE];
    __shared__ float cs_s[KK];
    int tid = threadIdx.x;
    if (tid < FE) inv_s[tid] = 1.f / fmaxf(sqrtf(g_ssq[tid]), 1e-12f);
    if (tid < KK) cs_s[tid] = 0.f;
    __syncthreads();
    for (int i = tid; i < KK*16; i += 256) {
        float4 w = reinterpret_cast<const float4*>(cen)[i];
        int f0 = (i*4) & 63;
        w.x *= inv_s[f0]; w.y *= inv_s[f0+1]; w.z *= inv_s[f0+2]; w.w *= inv_s[f0+3];
        cen_s[i] = w;
    }
    __syncthreads();

    int idx = blockIdx.x*256 + tid;              // (n, c-quarter)
    int n = idx >> 2, c0 = (idx & 3) * 16;
    float fr[FE];
    const float4* frp = reinterpret_cast<const float4*>(g_fea + n*FE);
#pragma unroll
    for (int f4 = 0; f4 < 16; f4++) {
        float4 v = frp[f4];
        fr[f4*4] = v.x; fr[f4*4+1] = v.y; fr[f4*4+2] = v.z; fr[f4*4+3] = v.w;
    }
#pragma unroll
    for (int cc = 0; cc < 16; cc++) {
        int c = c0 + cc;
        const float4* cr = cen_s + c*16;
        float l = 0.f;
#pragma unroll
        for (int f4 = 0; f4 < 16; f4++) {
            float4 w = cr[f4];
            l += fr[f4*4]*w.x + fr[f4*4+1]*w.y + fr[f4*4+2]*w.z + fr[f4*4+3]*w.w;
        }
        float e = __expf(l);
        g_expl[n*KK + c] = e;
        atomicAdd(&cs_s[c], e);
    }
    __syncthreads();
    if (tid < KK) atomicAdd(&g_colsum[tid], cs_s[tid]);
}

// ------------------------- k5a: newcacc = E^T @ fea (tiled GEMM) ------------
__global__ __launch_bounds__(256) void k5a_gemm() {
    __shared__ float e_s[32][68];
    __shared__ float f_s[32][68];
    int tid = threadIdx.x;
    int n0 = blockIdx.x * 32;
#pragma unroll
    for (int k = 0; k < 8; k++) {
        int idx = k*256 + tid;
        int r = idx >> 6, c = idx & 63;
        e_s[r][c] = g_expl[(n0 + r)*KK + c];
        f_s[r][c] = g_fea [(n0 + r)*FE + c];
    }
    __syncthreads();

    int c0 = (tid >> 4) * 4;
    int f0 = (tid & 15) * 4;
    float a00=0,a01=0,a02=0,a03=0, a10=0,a11=0,a12=0,a13=0;
    float a20=0,a21=0,a22=0,a23=0, a30=0,a31=0,a32=0,a33=0;
#pragma unroll 8
    for (int n = 0; n < 32; n++) {
        float4 e4 = *reinterpret_cast<const float4*>(&e_s[n][c0]);
        float4 f4 = *reinterpret_cast<const float4*>(&f_s[n][f0]);
        a00 += e4.x*f4.x; a01 += e4.x*f4.y; a02 += e4.x*f4.z; a03 += e4.x*f4.w;
        a10 += e4.y*f4.x; a11 += e4.y*f4.y; a12 += e4.y*f4.z; a13 += e4.y*f4.w;
        a20 += e4.z*f4.x; a21 += e4.z*f4.y; a22 += e4.z*f4.z; a23 += e4.z*f4.w;
        a30 += e4.w*f4.x; a31 += e4.w*f4.y; a32 += e4.w*f4.z; a33 += e4.w*f4.w;
    }
    float* base = g_newcacc + c0*FE + f0;
    atomicAdd(base+0,      a00); atomicAdd(base+1,      a01);
    atomicAdd(base+2,      a02); atomicAdd(base+3,      a03);
    atomicAdd(base+FE+0,   a10); atomicAdd(base+FE+1,   a11);
    atomicAdd(base+FE+2,   a12); atomicAdd(base+FE+3,   a13);
    atomicAdd(base+2*FE+0, a20); atomicAdd(base+2*FE+1, a21);
    atomicAdd(base+2*FE+2, a22); atomicAdd(base+2*FE+3, a23);
    atomicAdd(base+3*FE+0, a30); atomicAdd(base+3*FE+1, a31);
    atomicAdd(base+3*FE+2, a32); atomicAdd(base+3*FE+3, a33);
}

// ------------------------- k5b: normalize + kv + M/d fold -------------------
__global__ __launch_bounds__(128) void k5b_kv(const float* __restrict__ kv_w,
                                              const float* __restrict__ kv_b,
                                              const float* __restrict__ qw,
                                              const float* __restrict__ qb) {
    int c = blockIdx.x;                          // grid 64
    int tid = threadIdx.x;
    __shared__ float nc_s[FE], k_s[FE];
    if (tid < FE) {
        float inv = 1.f / fmaxf(sqrtf(g_ssq[tid]), 1e-12f);
        nc_s[tid] = g_newcacc[c*FE + tid] * inv / g_colsum[c];
    }
    __syncthreads();
    {                                            // kv projection
        float a = kv_b[tid];
        const float* wr = kv_w + tid*FE;
#pragma unroll
        for (int f = 0; f < FE; f++) a += nc_s[f] * wr[f];
        if (tid < 64) k_s[tid] = a;
        else          g_v[c*FE + (tid - 64)] = a;
    }
    __syncthreads();
    if (tid < 64) {                              // M fold
        float m = 0.f;
#pragma unroll 8
        for (int j = 0; j < FE; j++) m += k_s[j] * qw[j*FE + tid];
        float inv = 1.f / fmaxf(sqrtf(g_ssq[tid]), 1e-12f);
        g_M[c*FE + tid] = 0.125f * inv * m;
    } else if (tid == 64) {                      // d fold
        float dd = 0.f;
        for (int j = 0; j < FE; j++) dd += qb[j] * k_s[j];
        g_d[c] = 0.125f * dd;
    }
}

// ------------------------- kAttn: logits -> softmax -> @v -> scatter --------
__global__ __launch_bounds__(64) void kAttn() {
    __shared__ float M_s[KK*FE];                  // 16 KB
    __shared__ float v_s[KK*FE];                  // 16 KB
    __shared__ float d_s[KK];
    int tid = threadIdx.x;
    for (int i = tid; i < KK*FE; i += 64) { M_s[i] = g_M[i]; v_s[i] = g_v[i]; }
    if (tid < KK) d_s[tid] = g_d[tid];
    __syncthreads();

    int n = blockIdx.x*64 + tid;                  // token id, grid NT/64
    float fr[FE];
    const float4* frp = reinterpret_cast<const float4*>(g_fea + n*FE);
#pragma unroll
    for (int f4 = 0; f4 < 16; f4++) {
        float4 v = frp[f4];
        fr[f4*4] = v.x; fr[f4*4+1] = v.y; fr[f4*4+2] = v.z; fr[f4*4+3] = v.w;
    }
    float a[KK];
    float mx = -1e30f;
#pragma unroll 4
    for (int c = 0; c < KK; c++) {
        const float4* mr = reinterpret_cast<const float4*>(M_s + c*FE);
        float l = d_s[c];
#pragma unroll
        for (int f4 = 0; f4 < 16; f4++) {
            float4 w = mr[f4];
            l += fr[f4*4]*w.x + fr[f4*4+1]*w.y + fr[f4*4+2]*w.z + fr[f4*4+3]*w.w;
        }
        a[c] = l;
        mx = fmaxf(mx, l);
    }
    float s = 0.f;
#pragma unroll
    for (int c = 0; c < KK; c++) { a[c] = __expf(a[c] - mx); s += a[c]; }
    float si = 1.f / s;

    float acc[FE];
#pragma unroll
    for (int f = 0; f < FE; f++) acc[f] = 0.f;
#pragma unroll 4
    for (int c = 0; c < KK; c++) {
        float ac = a[c] * si;
        const float4* vr = reinterpret_cast<const float4*>(v_s + c*FE);
#pragma unroll
        for (int f4 = 0; f4 < 16; f4++) {
            float4 v = vr[f4];
            acc[f4*4]   += ac*v.x; acc[f4*4+1] += ac*v.y;
            acc[f4*4+2] += ac*v.z; acc[f4*4+3] += ac*v.w;
        }
    }
    int xb = n & 31, yb = (n >> 5) & 31, zb = n >> 10;
#pragma unroll
    for (int f4 = 0; f4 < 16; f4++) {
        int pz = f4 >> 2, py = f4 & 3;
        int p = ((zb*4 + pz)*HH + (yb*4 + py))*WW + xb*4;
        *reinterpret_cast<float4*>(g_o1 + p) =
            make_float4(acc[f4*4], acc[f4*4+1], acc[f4*4+2], acc[f4*4+3]);
    }
}

// ------------------------- k9: upc conv as GEMM + residual ------------------
// Block = 128 voxels = one (z,y) row.  OUT[128,96] = A[128,32]·W[32,96] + x + b
// A = o1 taps (bf16, taps 27..31 zero), W = upc_w (bf16). Same verified
// m16n8k16 fragment scheme as k1. Epilogue: float2 RMW of out with x + bias.
__global__ __launch_bounds__(128) void k9_mma(const float* __restrict__ x,
                                              const float* __restrict__ uw,
                                              const float* __restrict__ ub,
                                              float* __restrict__ out) {
    __shared__ float    os[9*132];       // o1 window rows (halo + zero pad)
    __shared__ uint32_t as[128*20];      // A: bf16x2 (tap 2m, 2m+1), pitch 20
    __shared__ uint32_t ws[16*104];      // B: bf16x2 (W[2m][n], W[2m+1][n])
    __shared__ float    bias_s[CC];
    int tid = threadIdx.x, lane = tid & 31, wid = tid >> 5;
    int g = lane >> 2, tg = lane & 3;

    // weights: W[t][n] = uw[n*27+t], taps >=27 zero
    for (int i = tid; i < 16*96; i += 128) {
        int m = i / 96, n = i % 96;
        int t0 = 2*m, t1 = 2*m + 1;
        float w0 = (t0 < 27) ? uw[n*27 + t0] : 0.f;
        float w1 = (t1 < 27) ? uw[n*27 + t1] : 0.f;
        __nv_bfloat162 h = __floats2bfloat162_rn(w0, w1);
        ws[m*104 + n] = *reinterpret_cast<uint32_t*>(&h);
    }
    if (tid < CC) bias_s[tid] = ub[tid];

    int z = blockIdx.x >> 7, y = blockIdx.x & 127;
    int v0 = blockIdx.x * 128;

    // o1 window: 9 (dz,dy) rows x 130 cols (x halo), zeros at borders
    for (int i = tid; i < 9*130; i += 128) {
        int row = i / 130, col = i % 130;
        int gz = z + row/3 - 1, gy = y + row%3 - 1, gx = col - 1;
        float v = 0.f;
        if ((unsigned)gz < DD && (unsigned)gy < HH && (unsigned)gx < WW)
            v = g_o1[(gz*HH + gy)*WW + gx];
        os[row*132 + col] = v;
    }
    __syncthreads();

    // A[v][taps]: v = tid, tap t = kz*9+ky*3+kx -> os[(kz*3+ky)*132 + v + kx]
    {
        int v = tid;
#pragma unroll
        for (int m = 0; m < 16; m++) {
            int t0 = 2*m, t1 = 2*m + 1;
            float a0 = 0.f, a1 = 0.f;
            if (t0 < 27) a0 = os[(t0/9*3 + (t0%9)/3)*132 + v + t0%3];
            if (t1 < 27) a1 = os[(t1/9*3 + (t1%9)/3)*132 + v + t1%3];
            __nv_bfloat162 h = __floats2bfloat162_rn(a0, a1);
            as[v*20 + m] = *reinterpret_cast<uint32_t*>(&h);
        }
    }
    __syncthreads();

    float c[2][12][4];
#pragma unroll
    for (int tl = 0; tl < 2; tl++)
#pragma unroll
        for (int nt = 0; nt < 12; nt++)
#pragma unroll
            for (int j = 0; j < 4; j++) c[tl][nt][j] = 0.f;

#pragma unroll
    for (int tl = 0; tl < 2; tl++) {
        int vloc = wid*32 + tl*16 + g;
#pragma unroll
        for (int ks = 0; ks < 2; ks++) {
            int m0 = ks*8 + tg;
            uint32_t a0 = as[vloc*20 + m0];
            uint32_t a1 = as[(vloc+8)*20 + m0];
            uint32_t a2 = as[vloc*20 + m0 + 4];
            uint32_t a3 = as[(vloc+8)*20 + m0 + 4];
#pragma unroll
            for (int nt = 0; nt < 12; nt++) {
                uint32_t b0 = ws[(ks*8 + tg)*104     + nt*8 + g];
                uint32_t b1 = ws[(ks*8 + tg + 4)*104 + nt*8 + g];
                mma16816(c[tl][nt], a0, a1, a2, a3, b0, b1);
            }
        }
    }

    // epilogue: out[v][n] = conv + x[v][n] + bias[n], float2 lanes
#pragma unroll
    for (int tl = 0; tl < 2; tl++) {
        int r0 = wid*32 + tl*16 + g;
#pragma unroll
        for (int nt = 0; nt < 12; nt++) {
            int n = nt*8 + tg*2;
            float b0 = bias_s[n], b1 = bias_s[n+1];
            {
                size_t idx = (size_t)(v0 + r0)*CC + n;
                float2 xv = *reinterpret_cast<const float2*>(x + idx);
                *reinterpret_cast<float2*>(out + idx) =
                    make_float2(xv.x + b0 + c[tl][nt][0],
                                xv.y + b1 + c[tl][nt][1]);
            }
            {
                size_t idx = (size_t)(v0 + r0 + 8)*CC + n;
                float2 xv = *reinterpret_cast<const float2*>(x + idx);
                *reinterpret_cast<float2*>(out + idx) =
                    make_float2(xv.x + b0 + c[tl][nt][2],
                                xv.y + b1 + c[tl][nt][3]);
            }
        }
    }
}

// ------------------------- launch --------------------------------------------
extern "C" void kernel_launch(void* const* d_in, const int* in_sizes, int n_in,
                              void* d_out, int out_size) {
    const float* x     = (const float*)d_in[0];
    const float* cen   = (const float*)d_in[1];
    const float* dwc_w = (const float*)d_in[2];
    const float* dwc_b = (const float*)d_in[3];
    const float* upc_w = (const float*)d_in[4];
    const float* upc_b = (const float*)d_in[5];
    const float* q_w   = (const float*)d_in[6];
    const float* q_b   = (const float*)d_in[7];
    const float* kv_w  = (const float*)d_in[8];
    const float* kv_b  = (const float*)d_in[9];
    float* out = (float*)d_out;

    init0     <<<1, 128>>>();
    init12    <<<1, 256>>>();
    k1_mma    <<<NP/K1_VB, 128>>>(x, dwc_w);
    k2_gather <<<NP/256, 256>>>(dwc_b);         // 4th launch -> ncu profiles this
    k4b_logits<<<(NT*4)/256, 256>>>(cen);
    k5a_gemm  <<<NT/32, 256>>>();
    k5b_kv    <<<KK, 128>>>(kv_w, kv_b, q_w, q_b);
    kAttn     <<<NT/64, 64>>>();
    k9_mma    <<<NP/128, 128>>>(x, upc_w, upc_b, out);
}